// round 3
// baseline (speedup 1.0000x reference)
#include <cuda_runtime.h>
#include <cstdint>
#include <cstdio>

#define Bn 8
#define Fn 64
#define Dn 20
#define FSn 160
#define Tn (Fn*FSn)   // 10240
#define Hn 256
#define CL 8

// ---------------- scratch (device globals; no allocation) ----------------
__device__ float g_c1[Bn*Fn*128];
__device__ float g_c2[Bn*Fn*128];
__device__ float g_cond[Bn*Fn*128];

// ---------------- helpers ----------------
__device__ __forceinline__ uint32_t cl_rank(){
    uint32_t r; asm("mov.u32 %0, %%cluster_ctarank;" : "=r"(r)); return r;
}
__device__ __forceinline__ uint32_t sm2u(const void* p){
    return (uint32_t)__cvta_generic_to_shared(p);
}
__device__ __forceinline__ void st_cl_f32(uint32_t laddr, uint32_t rank, float v){
    uint32_t ra;
    asm volatile("mapa.shared::cluster.u32 %0, %1, %2;" : "=r"(ra) : "r"(laddr), "r"(rank));
    asm volatile("st.shared::cluster.f32 [%0], %1;" :: "r"(ra), "f"(v) : "memory");
}
__device__ __forceinline__ void st_cl_s32(uint32_t laddr, uint32_t rank, int v){
    uint32_t ra;
    asm volatile("mapa.shared::cluster.u32 %0, %1, %2;" : "=r"(ra) : "r"(laddr), "r"(rank));
    asm volatile("st.shared::cluster.u32 [%0], %1;" :: "r"(ra), "r"(v) : "memory");
}
__device__ __forceinline__ void cl_arrive(){ asm volatile("barrier.cluster.arrive.aligned;" ::: "memory"); }
__device__ __forceinline__ void cl_wait(){ asm volatile("barrier.cluster.wait.aligned;" ::: "memory"); }

__device__ __forceinline__ float fsigm(float x){ return 1.f/(1.f + __expf(-x)); }
__device__ __forceinline__ float ftanh(float x){
    x = fminf(fmaxf(x, -10.f), 10.f);
    float e = __expf(2.f*x);
    return (e - 1.f)/(e + 1.f);
}

// ---------------- FrameRateNet (tiny, 3 kernels) ----------------
__global__ void frn_conv1(const float* __restrict__ feat,
                          const float* __restrict__ w,
                          const float* __restrict__ bias){
    int bf = blockIdx.x; int b = bf >> 6, f = bf & 63;
    int o = threadIdx.x;
    float acc = bias[o];
#pragma unroll
    for (int k = 0; k < 3; k++){
        int ff = f + k - 1;
        if (ff < 0 || ff >= Fn) continue;
        const float* fr = feat + (b*Fn + ff)*Dn;
#pragma unroll
        for (int i = 0; i < Dn; i++) acc += fr[i]*w[(k*Dn + i)*128 + o];
    }
    g_c1[bf*128 + o] = tanhf(acc);
}

__global__ void frn_conv2(const float* __restrict__ w,
                          const float* __restrict__ bias){
    __shared__ float srow[3*128];
    int bf = blockIdx.x; int b = bf >> 6, f = bf & 63;
    int o = threadIdx.x;
#pragma unroll
    for (int k = 0; k < 3; k++){
        int ff = f + k - 1;
        srow[k*128 + o] = (ff >= 0 && ff < Fn) ? g_c1[(b*Fn + ff)*128 + o] : 0.f;
    }
    __syncthreads();
    float acc = bias[o];
#pragma unroll 1
    for (int k = 0; k < 3; k++)
        for (int i = 0; i < 128; i++)
            acc += srow[k*128 + i]*w[(k*128 + i)*128 + o];
    g_c2[bf*128 + o] = tanhf(acc);
}

__global__ void frn_fc(const float* __restrict__ w1, const float* __restrict__ b1,
                       const float* __restrict__ w2, const float* __restrict__ b2){
    __shared__ float sv[128], sm_[128];
    int bf = blockIdx.x; int o = threadIdx.x;
    sv[o] = g_c2[bf*128 + o];
    __syncthreads();
    float a = b1[o];
    for (int j = 0; j < 128; j++) a += sv[j]*w1[j*128 + o];
    sm_[o] = tanhf(a);
    __syncthreads();
    float c = b2[o];
    for (int i = 0; i < 128; i++) c += sm_[i]*w2[i*128 + o];
    g_cond[bf*128 + o] = tanhf(c);
}

// ---------------- persistent autoregressive GRU ----------------
// grid = 64 CTAs, clusters of 8 (one cluster per batch). CTA rank c owns
// hidden units [32c, 32c+32). 256 threads = 32 unit-groups x 8 lanes.
// Weights live in REGISTERS (~179 weight regs/thread).
__global__ void __launch_bounds__(256, 1) __cluster_dims__(CL, 1, 1)
gru_kernel(const float* __restrict__ wi_g, const float* __restrict__ wh_g,
           const float* __restrict__ bi_g, const float* __restrict__ bh_g,
           const float* __restrict__ ow_g, const float* __restrict__ ob_g,
           float* __restrict__ wav_out, float* __restrict__ logits_out)
{
    __shared__ float sh_h[2][256];    // double-buffered hidden state (full 256)
    __shared__ float sh_P[CL][32];    // partial-logit scatter-reduce slices
    __shared__ float sh_mv[CL];       // per-CTA local max value
    __shared__ int   sh_mi[CL];       // per-CTA local argmax index
    __shared__ float sh_cond[144];    // current frame conditioning (padded, tail zeros)

    const int tid  = threadIdx.x;
    const int rank = (int)cl_rank();
    const int b    = blockIdx.x / CL;
    const int lane = tid & 31;
    const int jl   = (tid >> 5)*4 + (lane >> 3);  // local unit 0..31
    const int s    = lane & 7;                    // k-stripe 0..7
    const int u    = rank*32 + jl;                // global hidden unit

    // ---- load weights into registers (fully unrolled -> register arrays) ----
    float whr[32], whz[32], whn[32];
#pragma unroll
    for (int m = 0; m < 32; m++){
        int k = s + 8*m;
        whr[m] = wh_g[(u      )*256 + k];
        whz[m] = wh_g[(256 + u)*256 + k];
        whn[m] = wh_g[(512 + u)*256 + k];
    }
    float wir[17], wiz[17], win[17];
#pragma unroll
    for (int m = 0; m < 17; m++){
        int k = s + 8*m;
        if (k < 129){
            wir[m] = wi_g[(u      )*129 + k];
            wiz[m] = wi_g[(256 + u)*129 + k];
            win[m] = wi_g[(512 + u)*129 + k];
        } else { wir[m] = 0.f; wiz[m] = 0.f; win[m] = 0.f; }
    }
    float ow[32];
#pragma unroll
    for (int j2 = 0; j2 < 32; j2++) ow[j2] = ow_g[(rank*32 + j2)*256 + tid];
    const float ob  = (tid < 32) ? ob_g[rank*32 + tid] : 0.f;
    const float bir = bi_g[u],     biz = bi_g[256 + u], bin_ = bi_g[512 + u];
    const float bhr = bh_g[u],     bhz = bh_g[256 + u], bhn  = bh_g[512 + u];

    // ---- init shared state ----
    for (int i = tid; i < 2*256; i += 256) ((float*)sh_h)[i] = 0.f;
    if (tid >= 128 && tid < 144) sh_cond[tid] = 0.f;
    if (tid < 128) sh_cond[tid] = g_cond[(b*Fn + 0)*128 + tid];
    __syncthreads();
    cl_arrive(); cl_wait();   // peers' smem init complete before remote writes

    const uint32_t h_base = sm2u(&sh_h[0][0]);
    const uint32_t P_addr = sm2u(&sh_P[rank][lane]);
    float prev = 0.f, y = 0.f;

    for (int t = 0; t < Tn; ++t){
        const int p = t & 1;
        // ---------- phase 1: gates ----------
        float ahr = 0.f, ahz = 0.f, ahn = 0.f, air = 0.f, aiz = 0.f, ain = 0.f;
        const float* hp = sh_h[p];
#pragma unroll
        for (int m = 0; m < 32; m++){
            float hv = hp[s + 8*m];           // conflict-free broadcast LDS
            ahr += whr[m]*hv; ahz += whz[m]*hv; ahn += whn[m]*hv;
        }
        {
            float xv = (s == 0) ? prev : sh_cond[s - 1];
            air += wir[0]*xv; aiz += wiz[0]*xv; ain += win[0]*xv;
        }
#pragma unroll
        for (int m = 1; m < 17; m++){
            float xv = sh_cond[s + 8*m - 1];  // tail pads are zero; oob weights are zero
            air += wir[m]*xv; aiz += wiz[m]*xv; ain += win[m]*xv;
        }
        // reduce over the 8-lane group (xor: all lanes get totals)
#pragma unroll
        for (int off = 4; off >= 1; off >>= 1){
            ahr += __shfl_xor_sync(0xffffffffu, ahr, off);
            ahz += __shfl_xor_sync(0xffffffffu, ahz, off);
            ahn += __shfl_xor_sync(0xffffffffu, ahn, off);
            air += __shfl_xor_sync(0xffffffffu, air, off);
            aiz += __shfl_xor_sync(0xffffffffu, aiz, off);
            ain += __shfl_xor_sync(0xffffffffu, ain, off);
        }
        float rg   = fsigm(air + bir + ahr + bhr);
        float zg   = fsigm(aiz + biz + ahz + bhz);
        float ng   = ftanh(ain + bin_ + rg*(ahn + bhn));
        float hold = hp[u];
        float hnew = (1.f - zg)*ng + zg*hold;

        // distribute h_new: lane s delivers this unit's value to CTA rank s
        {
            uint32_t la = h_base + (uint32_t)((((p ^ 1)*256) + u)*4);
            if (s == rank) sh_h[p ^ 1][u] = hnew;
            else           st_cl_f32(la, (uint32_t)s, hnew);
        }
        __syncthreads();  // local h_new slice visible for partial logits

        // partial logits from LOCAL h slice, scatter-reduce to owning CTA
        float pv = 0.f;
        const float* hq = sh_h[p ^ 1] + rank*32;
#pragma unroll
        for (int j2 = 0; j2 < 32; j2++) pv += hq[j2]*ow[j2];
        {
            int d = tid >> 5;                  // dest rank owns columns [32d,32d+32)
            if (d == rank) sh_P[rank][lane] = pv;
            else           st_cl_f32(P_addr, (uint32_t)d, pv);
        }
        cl_arrive();
        cl_wait();

        // ---------- phase 2: final logits, argmax exchange ----------
        float logit = 0.f;
        if (tid < 32){
            logit = ob;
#pragma unroll
            for (int src = 0; src < CL; src++) logit += sh_P[src][tid];
        }
        if ((tid >> 5) == 0){
            float mv = logit; int mi = rank*32 + lane;
#pragma unroll
            for (int off = 16; off >= 1; off >>= 1){
                float ov = __shfl_down_sync(0xffffffffu, mv, off);
                int   oi = __shfl_down_sync(0xffffffffu, mi, off);
                if (ov > mv || (ov == mv && oi < mi)){ mv = ov; mi = oi; }
            }
            if (lane == 0){
                uint32_t mva = sm2u(&sh_mv[rank]);
                uint32_t mia = sm2u(&sh_mi[rank]);
#pragma unroll
                for (int d = 0; d < CL; d++){
                    if (d == rank){ sh_mv[rank] = mv; sh_mi[rank] = mi; }
                    else { st_cl_f32(mva, (uint32_t)d, mv); st_cl_s32(mia, (uint32_t)d, mi); }
                }
            }
        }
        cl_arrive();
        if (tid < 32){   // overlap the logits STG with the barrier
            logits_out[((size_t)(b*Tn + t))*256 + rank*32 + tid] = logit;
        }
        cl_wait();

        // ---------- combine, mu-law sample, de-emphasis ----------
        float bmv = sh_mv[0]; int bmi = sh_mi[0];
#pragma unroll
        for (int sc = 1; sc < CL; sc++){
            float v2 = sh_mv[sc]; int i2 = sh_mi[sc];
            if (v2 > bmv || (v2 == bmv && i2 < bmi)){ bmv = v2; bmi = i2; }
        }
        float v   = ((float)bmi + 0.5f)*(1.f/128.f) - 1.f;
        float av  = fabsf(v);
        float smp = copysignf((exp2f(8.f*av) - 1.f)*(1.f/255.f), v);  // 256^|v| = 2^(8|v|)
        prev = smp;
        if (rank == 0 && tid == 0){
            y = smp + 0.97f*y;
            wav_out[b*Tn + t] = y;
        }
        int tn = t + 1;
        if (tn < Tn && (tn % FSn) == 0){
            if (tid < 128) sh_cond[tid] = g_cond[(b*Fn + tn/FSn)*128 + tid];
        }
        __syncthreads();
    }
}

// ---------------- launch ----------------
extern "C" void kernel_launch(void* const* d_in, const int* in_sizes, int n_in,
                              void* d_out, int out_size)
{
    const float* features = (const float*)d_in[0];
    const float* c1w = (const float*)d_in[1];
    const float* c1b = (const float*)d_in[2];
    const float* c2w = (const float*)d_in[3];
    const float* c2b = (const float*)d_in[4];
    const float* f1w = (const float*)d_in[5];
    const float* f1b = (const float*)d_in[6];
    const float* f2w = (const float*)d_in[7];
    const float* f2b = (const float*)d_in[8];
    const float* wi  = (const float*)d_in[9];
    const float* wh  = (const float*)d_in[10];
    const float* bi  = (const float*)d_in[11];
    const float* bh  = (const float*)d_in[12];
    const float* oww = (const float*)d_in[13];
    const float* obb = (const float*)d_in[14];

    float* out    = (float*)d_out;
    float* wav    = out;                       // (B, T, 1) flattened first
    float* logits = out + (size_t)Bn*Tn;       // (B, T, 256) after

    frn_conv1<<<Bn*Fn, 128>>>(features, c1w, c1b);
    frn_conv2<<<Bn*Fn, 128>>>(c2w, c2b);
    frn_fc   <<<Bn*Fn, 128>>>(f1w, f1b, f2w, f2b);
    gru_kernel<<<Bn*CL, 256>>>(wi, wh, bi, bh, oww, obb, wav, logits);
}

// round 6
// speedup vs baseline: 1.9987x; 1.9987x over previous
#include <cuda_runtime.h>
#include <cstdint>

#define Bn 8
#define Fn 64
#define Dn 20
#define FSn 160
#define Tn (Fn*FSn)   // 10240
#define CL 8

// ---------------- scratch (device globals; no allocation) ----------------
__device__ float g_c1[Bn*Fn*128];
__device__ float g_c2[Bn*Fn*128];
__device__ float g_cond[Bn*Fn*128];

// ---------------- helpers ----------------
__device__ __forceinline__ uint32_t cl_rank(){
    uint32_t r; asm("mov.u32 %0, %%cluster_ctarank;" : "=r"(r)); return r;
}
__device__ __forceinline__ uint32_t sm2u(const void* p){
    return (uint32_t)__cvta_generic_to_shared(p);
}
__device__ __forceinline__ void st_cl_f32(uint32_t laddr, uint32_t rank, float v){
    uint32_t ra;
    asm volatile("mapa.shared::cluster.u32 %0, %1, %2;" : "=r"(ra) : "r"(laddr), "r"(rank));
    asm volatile("st.shared::cluster.f32 [%0], %1;" :: "r"(ra), "f"(v) : "memory");
}
__device__ __forceinline__ void st_cl_u64(uint32_t laddr, uint32_t rank, unsigned long long v){
    uint32_t ra;
    asm volatile("mapa.shared::cluster.u32 %0, %1, %2;" : "=r"(ra) : "r"(laddr), "r"(rank));
    asm volatile("st.shared::cluster.u64 [%0], %1;" :: "r"(ra), "l"(v) : "memory");
}
__device__ __forceinline__ void cl_arrive(){ asm volatile("barrier.cluster.arrive.aligned;" ::: "memory"); }
__device__ __forceinline__ void cl_wait(){ asm volatile("barrier.cluster.wait.aligned;" ::: "memory"); }

__device__ __forceinline__ float fsigm(float x){ return 1.f/(1.f + __expf(-x)); }
__device__ __forceinline__ float ftanh(float x){
    x = fminf(fmaxf(x, -10.f), 10.f);
    float e = __expf(2.f*x);
    return (e - 1.f)/(e + 1.f);
}
// monotone float->uint map (larger float => larger uint), finite inputs
__device__ __forceinline__ uint32_t ford(float f){
    uint32_t u = __float_as_uint(f);
    return (u & 0x80000000u) ? ~u : (u | 0x80000000u);
}

// ---------------- FrameRateNet (tiny, 3 kernels) ----------------
__global__ void frn_conv1(const float* __restrict__ feat,
                          const float* __restrict__ w,
                          const float* __restrict__ bias){
    int bf = blockIdx.x; int b = bf >> 6, f = bf & 63;
    int o = threadIdx.x;
    float acc = bias[o];
#pragma unroll
    for (int k = 0; k < 3; k++){
        int ff = f + k - 1;
        if (ff < 0 || ff >= Fn) continue;
        const float* fr = feat + (b*Fn + ff)*Dn;
#pragma unroll
        for (int i = 0; i < Dn; i++) acc += fr[i]*w[(k*Dn + i)*128 + o];
    }
    g_c1[bf*128 + o] = tanhf(acc);
}

__global__ void frn_conv2(const float* __restrict__ w,
                          const float* __restrict__ bias){
    __shared__ float srow[3*128];
    int bf = blockIdx.x; int b = bf >> 6, f = bf & 63;
    int o = threadIdx.x;
#pragma unroll
    for (int k = 0; k < 3; k++){
        int ff = f + k - 1;
        srow[k*128 + o] = (ff >= 0 && ff < Fn) ? g_c1[(b*Fn + ff)*128 + o] : 0.f;
    }
    __syncthreads();
    float acc = bias[o];
#pragma unroll 1
    for (int k = 0; k < 3; k++)
        for (int i = 0; i < 128; i++)
            acc += srow[k*128 + i]*w[(k*128 + i)*128 + o];
    g_c2[bf*128 + o] = tanhf(acc);
}

__global__ void frn_fc(const float* __restrict__ w1, const float* __restrict__ b1,
                       const float* __restrict__ w2, const float* __restrict__ b2){
    __shared__ float sv[128], sm_[128];
    int bf = blockIdx.x; int o = threadIdx.x;
    sv[o] = g_c2[bf*128 + o];
    __syncthreads();
    float a = b1[o];
    for (int j = 0; j < 128; j++) a += sv[j]*w1[j*128 + o];
    sm_[o] = tanhf(a);
    __syncthreads();
    float c = b2[o];
    for (int i = 0; i < 128; i++) c += sm_[i]*w2[i*128 + o];
    g_cond[bf*128 + o] = tanhf(c);
}

// ---------------- persistent autoregressive GRU ----------------
// 64 CTAs, clusters of 8 (one per batch). CTA rank c owns hidden units
// [32c,32c+32). 256 threads = 32 unit-groups x 8 k-stripes. All recurrent
// weights in registers. Software-pipelined: next step's W_hh·h is computed
// between arrive(B) and wait(B); the cond·W_i part is hoisted per-frame.
__global__ void __launch_bounds__(256, 1) __cluster_dims__(CL, 1, 1)
gru_kernel(const float* __restrict__ wi_g, const float* __restrict__ wh_g,
           const float* __restrict__ bi_g, const float* __restrict__ bh_g,
           const float* __restrict__ ow_g, const float* __restrict__ ob_g,
           float* __restrict__ wav_out, float* __restrict__ logits_out)
{
    __shared__ float sh_h[2][256];              // double-buffered hidden state
    __shared__ float sh_P[CL][32];              // partial-logit scatter slices
    __shared__ unsigned long long sh_enc[CL];   // per-CTA encoded (max,idx)
    __shared__ float sh_cond[128];              // current-frame conditioning

    const int tid  = threadIdx.x;
    const int rank = (int)cl_rank();
    const int b    = blockIdx.x / CL;
    const int lane = tid & 31;
    const int jl   = (tid >> 5)*4 + (lane >> 3);  // local unit 0..31
    const int s    = lane & 7;                    // k-stripe 0..7
    const int u    = rank*32 + jl;                // global hidden unit

    // ---- recurrent weights into registers ----
    float whr[32], whz[32], whn[32];
#pragma unroll
    for (int m = 0; m < 32; m++){
        int k = s + 8*m;
        whr[m] = wh_g[(u      )*256 + k];
        whz[m] = wh_g[(256 + u)*256 + k];
        whn[m] = wh_g[(512 + u)*256 + k];
    }
    // input weights: col 0 (prev sample) separate; cols 1..128 (cond) striped
    const float wpr = wi_g[(u      )*129];
    const float wpz = wi_g[(256 + u)*129];
    const float wpn = wi_g[(512 + u)*129];
    float wcr[16], wcz[16], wcn[16];
#pragma unroll
    for (int m = 0; m < 16; m++){
        int k = 1 + s + 8*m;
        wcr[m] = wi_g[(u      )*129 + k];
        wcz[m] = wi_g[(256 + u)*129 + k];
        wcn[m] = wi_g[(512 + u)*129 + k];
    }
    float ow[32];
#pragma unroll
    for (int j2 = 0; j2 < 32; j2++) ow[j2] = ow_g[(rank*32 + j2)*256 + tid];
    const float ob  = (tid < 32) ? ob_g[rank*32 + tid] : 0.f;
    // bias folding: r,z gates fold bi+bh; n gate folds bi only (bh_n sits
    // inside the r-multiplied term per the GRU formula)
    const float bsr  = bi_g[u]       + bh_g[u];
    const float bsz  = bi_g[256 + u] + bh_g[256 + u];
    const float bin_ = bi_g[512 + u];
    const float bhn  = bh_g[512 + u];

    // ---- init shared state ----
    for (int i = tid; i < 2*256; i += 256) ((float*)sh_h)[i] = 0.f;
    if (tid < 128) sh_cond[tid] = g_cond[(b*Fn + 0)*128 + tid];
    __syncthreads();

    // per-frame conditioning constants (all 8 lanes of a group end with the sum)
    float cr, cz, cn;
    auto calc_consts = [&](){
        float tr = 0.f, tz = 0.f, tn2 = 0.f;
#pragma unroll
        for (int m = 0; m < 16; m++){
            float cv = sh_cond[s + 8*m];
            tr  = fmaf(wcr[m], cv, tr);
            tz  = fmaf(wcz[m], cv, tz);
            tn2 = fmaf(wcn[m], cv, tn2);
        }
#pragma unroll
        for (int off = 4; off >= 1; off >>= 1){
            tr  += __shfl_xor_sync(0xffffffffu, tr,  off);
            tz  += __shfl_xor_sync(0xffffffffu, tz,  off);
            tn2 += __shfl_xor_sync(0xffffffffu, tn2, off);
        }
        cr = tr + bsr; cz = tz + bsz; cn = tn2 + bin_;
    };
    calc_consts();

    cl_arrive(); cl_wait();   // peers' smem init complete before remote writes

    const uint32_t h_base   = sm2u(&sh_h[0][0]);
    const uint32_t P_addr   = sm2u(&sh_P[rank][lane]);
    const uint32_t enc_addr = sm2u(&sh_enc[rank]);

    float prev = 0.f, hold = 0.f, y = 0.f;
    float ahr = 0.f, ahz = 0.f, ahn = 0.f;   // pipelined W_hh·h partials (h_{-1}=0)

    for (int t = 0; t < Tn; ++t){
        const int bq = t & 1;

        // ---------- gates: reduce pipelined h-part, add per-frame consts ----------
#pragma unroll
        for (int off = 4; off >= 1; off >>= 1){
            ahr += __shfl_xor_sync(0xffffffffu, ahr, off);
            ahz += __shfl_xor_sync(0xffffffffu, ahz, off);
            ahn += __shfl_xor_sync(0xffffffffu, ahn, off);
        }
        float rg   = fsigm(ahr + cr + wpr*prev);
        float zg   = fsigm(ahz + cz + wpz*prev);
        float ng   = ftanh(cn + wpn*prev + rg*(ahn + bhn));
        float hnew = fmaf(zg, hold - ng, ng);    // (1-z)n + z*hold
        hold = hnew;

        // ---------- distribute h_new: lane s delivers to CTA rank s ----------
        if (s == rank) sh_h[bq][u] = hnew;
        else           st_cl_f32(h_base + (uint32_t)((bq*256 + u)*4), (uint32_t)s, hnew);
        __syncthreads();   // local slice visible for partial logits

        // partial logits from LOCAL h slice, scatter to owning CTA
        float pv = 0.f;
        const float* hq = sh_h[bq] + rank*32;
#pragma unroll
        for (int j2 = 0; j2 < 32; j2++) pv = fmaf(hq[j2], ow[j2], pv);
        {
            int d = tid >> 5;
            if (d == rank) sh_P[rank][lane] = pv;
            else           st_cl_f32(P_addr, (uint32_t)d, pv);
        }
        cl_arrive();                               // barrier A arrive

        // ---- gap before wait A: per-frame cond reload + const recompute ----
        int tn1 = t + 1;
        if (tn1 < Tn && (tn1 % FSn) == 0){
            __syncthreads();
            if (tid < 128) sh_cond[tid] = g_cond[(b*Fn + tn1/FSn)*128 + tid];
            __syncthreads();
            calc_consts();
        }
        cl_wait();                                 // barrier A wait

        // ---------- phase 2: final logits + encoded argmax (warp 0) ----------
        float logit = 0.f;
        unsigned long long enc = 0ull;
        if (tid < 32){
            logit = ob;
#pragma unroll
            for (int src = 0; src < CL; src++) logit += sh_P[src][tid];
            enc = ((unsigned long long)ford(logit) << 8)
                | (unsigned long long)(255 - (rank*32 + tid));
#pragma unroll
            for (int off = 16; off >= 1; off >>= 1){
                unsigned long long o = __shfl_xor_sync(0xffffffffu, enc, off);
                enc = (o > enc) ? o : enc;
            }
        }
        if (tid == 0){
#pragma unroll
            for (int d = 0; d < CL; d++){
                if (d == rank) sh_enc[rank] = enc;
                else           st_cl_u64(enc_addr, (uint32_t)d, enc);
            }
        }
        cl_arrive();                               // barrier B arrive

        // ---- hidden region: logits STG + next step's W_hh·h (96 FFMA) ----
        if (tid < 32)
            logits_out[((size_t)(b*Tn + t))*256 + rank*32 + tid] = logit;
        {
            const float* hp = sh_h[bq];
            float a0 = 0.f, a1 = 0.f, a2 = 0.f;
#pragma unroll
            for (int m = 0; m < 32; m++){
                float hv = hp[s + 8*m];            // conflict-free broadcast LDS
                a0 = fmaf(whr[m], hv, a0);
                a1 = fmaf(whz[m], hv, a1);
                a2 = fmaf(whn[m], hv, a2);
            }
            ahr = a0; ahz = a1; ahn = a2;
        }
        cl_wait();                                 // barrier B wait (mostly hidden)

        // ---------- combine argmax, mu-law sample, de-emphasis ----------
        unsigned long long best = sh_enc[0];
#pragma unroll
        for (int sc = 1; sc < CL; sc++){
            unsigned long long v2 = sh_enc[sc];
            best = (v2 > best) ? v2 : best;
        }
        int idx   = 255 - (int)(best & 0xFFull);
        float v   = ((float)idx + 0.5f)*(1.f/128.f) - 1.f;
        float av  = fabsf(v);
        float smp = copysignf((exp2f(8.f*av) - 1.f)*(1.f/255.f), v);
        prev = smp;
        if (rank == 0 && tid == 0){
            y = smp + 0.97f*y;
            wav_out[b*Tn + t] = y;
        }
    }
}

// ---------------- launch ----------------
extern "C" void kernel_launch(void* const* d_in, const int* in_sizes, int n_in,
                              void* d_out, int out_size)
{
    const float* features = (const float*)d_in[0];
    const float* c1w = (const float*)d_in[1];
    const float* c1b = (const float*)d_in[2];
    const float* c2w = (const float*)d_in[3];
    const float* c2b = (const float*)d_in[4];
    const float* f1w = (const float*)d_in[5];
    const float* f1b = (const float*)d_in[6];
    const float* f2w = (const float*)d_in[7];
    const float* f2b = (const float*)d_in[8];
    const float* wi  = (const float*)d_in[9];
    const float* wh  = (const float*)d_in[10];
    const float* bi  = (const float*)d_in[11];
    const float* bh  = (const float*)d_in[12];
    const float* oww = (const float*)d_in[13];
    const float* obb = (const float*)d_in[14];

    float* out    = (float*)d_out;
    float* wav    = out;                       // (B, T, 1) flattened first
    float* logits = out + (size_t)Bn*Tn;       // (B, T, 256) after

    frn_conv1<<<Bn*Fn, 128>>>(features, c1w, c1b);
    frn_conv2<<<Bn*Fn, 128>>>(c2w, c2b);
    frn_fc   <<<Bn*Fn, 128>>>(f1w, f1b, f2w, f2b);
    gru_kernel<<<Bn*CL, 256>>>(wi, wh, bi, bh, oww, obb, wav, logits);
}

// round 7
// speedup vs baseline: 2.5207x; 1.2612x over previous
#include <cuda_runtime.h>
#include <cstdint>

#define Bn 8
#define Fn 64
#define Dn 20
#define FSn 160
#define Tn (Fn*FSn)   // 10240
#define CL 8

// ---------------- scratch (device globals; no allocation) ----------------
__device__ float g_c1[Bn*Fn*128];
__device__ float g_c2[Bn*Fn*128];
__device__ float g_cond[Bn*Fn*128];

// ---------------- helpers ----------------
__device__ __forceinline__ uint32_t cl_rank(){
    uint32_t r; asm("mov.u32 %0, %%cluster_ctarank;" : "=r"(r)); return r;
}
__device__ __forceinline__ uint32_t sm2u(const void* p){
    return (uint32_t)__cvta_generic_to_shared(p);
}
__device__ __forceinline__ void cl_arrive(){ asm volatile("barrier.cluster.arrive.aligned;" ::: "memory"); }
__device__ __forceinline__ void cl_wait(){ asm volatile("barrier.cluster.wait.aligned;" ::: "memory"); }

__device__ __forceinline__ void mbar_init(uint32_t mbar, uint32_t cnt){
    asm volatile("mbarrier.init.shared.b64 [%0], %1;" :: "r"(mbar), "r"(cnt) : "memory");
}
__device__ __forceinline__ void mbar_arrive_expect(uint32_t mbar, uint32_t bytes){
    asm volatile("mbarrier.arrive.expect_tx.shared.b64 _, [%0], %1;" :: "r"(mbar), "r"(bytes) : "memory");
}
__device__ __forceinline__ void mbar_wait(uint32_t mbar, uint32_t parity){
    uint32_t done;
    do {
        asm volatile(
            "{\n\t.reg .pred p;\n\t"
            "mbarrier.try_wait.parity.acquire.cta.shared::cta.b64 p, [%1], %2, 0x989680;\n\t"
            "selp.b32 %0, 1, 0, p;\n\t}"
            : "=r"(done) : "r"(mbar), "r"(parity) : "memory");
    } while (!done);
}
// one-sided store into (possibly remote) cluster CTA smem, signaling that
// CTA's mbarrier with complete_tx bytes
__device__ __forceinline__ void st_async_f32(uint32_t dst_l, uint32_t mbar_l, uint32_t rank, float v){
    uint32_t rd, rm;
    asm volatile("mapa.shared::cluster.u32 %0, %1, %2;" : "=r"(rd) : "r"(dst_l), "r"(rank));
    asm volatile("mapa.shared::cluster.u32 %0, %1, %2;" : "=r"(rm) : "r"(mbar_l), "r"(rank));
    asm volatile("st.async.weak.shared::cluster.mbarrier::complete_tx::bytes.b32 [%0], %1, [%2];"
                 :: "r"(rd), "r"(__float_as_uint(v)), "r"(rm) : "memory");
}
__device__ __forceinline__ void st_async_u64(uint32_t dst_l, uint32_t mbar_l, uint32_t rank, unsigned long long v){
    uint32_t rd, rm;
    asm volatile("mapa.shared::cluster.u32 %0, %1, %2;" : "=r"(rd) : "r"(dst_l), "r"(rank));
    asm volatile("mapa.shared::cluster.u32 %0, %1, %2;" : "=r"(rm) : "r"(mbar_l), "r"(rank));
    asm volatile("st.async.weak.shared::cluster.mbarrier::complete_tx::bytes.b64 [%0], %1, [%2];"
                 :: "r"(rd), "l"(v), "r"(rm) : "memory");
}

__device__ __forceinline__ float fsigm(float x){ return 1.f/(1.f + __expf(-x)); }
__device__ __forceinline__ float ftanh(float x){
    x = fminf(fmaxf(x, -10.f), 10.f);
    float e = __expf(2.f*x);
    return (e - 1.f)/(e + 1.f);
}
// monotone float->uint map (larger float => larger uint), finite inputs
__device__ __forceinline__ uint32_t ford(float f){
    uint32_t u = __float_as_uint(f);
    return (u & 0x80000000u) ? ~u : (u | 0x80000000u);
}

// ---------------- FrameRateNet (tiny, 3 kernels) ----------------
__global__ void frn_conv1(const float* __restrict__ feat,
                          const float* __restrict__ w,
                          const float* __restrict__ bias){
    int bf = blockIdx.x; int b = bf >> 6, f = bf & 63;
    int o = threadIdx.x;
    float acc = bias[o];
#pragma unroll
    for (int k = 0; k < 3; k++){
        int ff = f + k - 1;
        if (ff < 0 || ff >= Fn) continue;
        const float* fr = feat + (b*Fn + ff)*Dn;
#pragma unroll
        for (int i = 0; i < Dn; i++) acc += fr[i]*w[(k*Dn + i)*128 + o];
    }
    g_c1[bf*128 + o] = tanhf(acc);
}

__global__ void frn_conv2(const float* __restrict__ w,
                          const float* __restrict__ bias){
    __shared__ float srow[3*128];
    int bf = blockIdx.x; int b = bf >> 6, f = bf & 63;
    int o = threadIdx.x;
#pragma unroll
    for (int k = 0; k < 3; k++){
        int ff = f + k - 1;
        srow[k*128 + o] = (ff >= 0 && ff < Fn) ? g_c1[(b*Fn + ff)*128 + o] : 0.f;
    }
    __syncthreads();
    float acc = bias[o];
#pragma unroll 1
    for (int k = 0; k < 3; k++)
        for (int i = 0; i < 128; i++)
            acc += srow[k*128 + i]*w[(k*128 + i)*128 + o];
    g_c2[bf*128 + o] = tanhf(acc);
}

__global__ void frn_fc(const float* __restrict__ w1, const float* __restrict__ b1,
                       const float* __restrict__ w2, const float* __restrict__ b2){
    __shared__ float sv[128], sm_[128];
    int bf = blockIdx.x; int o = threadIdx.x;
    sv[o] = g_c2[bf*128 + o];
    __syncthreads();
    float a = b1[o];
    for (int j = 0; j < 128; j++) a += sv[j]*w1[j*128 + o];
    sm_[o] = tanhf(a);
    __syncthreads();
    float c = b2[o];
    for (int i = 0; i < 128; i++) c += sm_[i]*w2[i*128 + o];
    g_cond[bf*128 + o] = tanhf(c);
}

// ---------------- persistent autoregressive GRU ----------------
// 64 CTAs, clusters of 8 (one per batch). CTA rank c owns hidden units
// [32c,32c+32). 256 threads = 32 unit-groups x 8 k-stripes. Recurrent
// weights in registers. All cross-CTA sync is one-sided st.async + mbarrier
// transaction counting (no barrier.cluster in the loop).
__global__ void __launch_bounds__(256, 1) __cluster_dims__(CL, 1, 1)
gru_kernel(const float* __restrict__ wi_g, const float* __restrict__ wh_g,
           const float* __restrict__ bi_g, const float* __restrict__ bh_g,
           const float* __restrict__ ow_g, const float* __restrict__ ob_g,
           float* __restrict__ wav_out, float* __restrict__ logits_out)
{
    __shared__ float sh_h[2][256];                    // double-buffered hidden state
    __shared__ float sh_P[2][CL][32];                 // partial-logit slices [buf][src][col]
    __shared__ unsigned long long sh_enc[2][CL];      // encoded (max,idx) per src CTA
    __shared__ float sh_cond[128];                    // current-frame conditioning
    __shared__ __align__(8) unsigned long long sh_mb[6];  // H0,H1,P0,P1,E0,E1

    const int tid  = threadIdx.x;
    const int rank = (int)cl_rank();
    const int b    = blockIdx.x / CL;
    const int lane = tid & 31;
    const int jl   = (tid >> 5)*4 + (lane >> 3);  // local unit 0..31
    const int s    = lane & 7;                    // k-stripe 0..7
    const int u    = rank*32 + jl;                // global hidden unit

    // ---- recurrent weights into registers ----
    float whr[32], whz[32], whn[32];
#pragma unroll
    for (int m = 0; m < 32; m++){
        int k = s + 8*m;
        whr[m] = wh_g[(u      )*256 + k];
        whz[m] = wh_g[(256 + u)*256 + k];
        whn[m] = wh_g[(512 + u)*256 + k];
    }
    const float wpr = wi_g[(u      )*129];
    const float wpz = wi_g[(256 + u)*129];
    const float wpn = wi_g[(512 + u)*129];
    float wcr[16], wcz[16], wcn[16];
#pragma unroll
    for (int m = 0; m < 16; m++){
        int k = 1 + s + 8*m;
        wcr[m] = wi_g[(u      )*129 + k];
        wcz[m] = wi_g[(256 + u)*129 + k];
        wcn[m] = wi_g[(512 + u)*129 + k];
    }
    float ow[32];
#pragma unroll
    for (int j2 = 0; j2 < 32; j2++) ow[j2] = ow_g[(rank*32 + j2)*256 + tid];
    const float ob  = (tid < 32) ? ob_g[rank*32 + tid] : 0.f;
    const float bsr  = bi_g[u]       + bh_g[u];
    const float bsz  = bi_g[256 + u] + bh_g[256 + u];
    const float bin_ = bi_g[512 + u];
    const float bhn  = bh_g[512 + u];

    // ---- init shared state + mbarriers ----
    for (int i = tid; i < 2*256; i += 256) ((float*)sh_h)[i] = 0.f;
    if (tid < 128) sh_cond[tid] = g_cond[(b*Fn + 0)*128 + tid];
    if (tid < 6) mbar_init(sm2u(&sh_mb[tid]), 1);
    __syncthreads();

    float cr, cz, cn;
    auto calc_consts = [&](){
        float tr = 0.f, tz = 0.f, tn2 = 0.f;
#pragma unroll
        for (int m = 0; m < 16; m++){
            float cv = sh_cond[s + 8*m];
            tr  = fmaf(wcr[m], cv, tr);
            tz  = fmaf(wcz[m], cv, tz);
            tn2 = fmaf(wcn[m], cv, tn2);
        }
#pragma unroll
        for (int off = 4; off >= 1; off >>= 1){
            tr  += __shfl_xor_sync(0xffffffffu, tr,  off);
            tz  += __shfl_xor_sync(0xffffffffu, tz,  off);
            tn2 += __shfl_xor_sync(0xffffffffu, tn2, off);
        }
        cr = tr + bsr; cz = tz + bsz; cn = tn2 + bin_;
    };
    calc_consts();

    cl_arrive(); cl_wait();   // one-time: peers' smem + mbarriers initialized

    const uint32_t mbH[2] = { sm2u(&sh_mb[0]), sm2u(&sh_mb[1]) };
    const uint32_t mbP[2] = { sm2u(&sh_mb[2]), sm2u(&sh_mb[3]) };
    const uint32_t mbE[2] = { sm2u(&sh_mb[4]), sm2u(&sh_mb[5]) };
    const uint32_t hA[2]  = { sm2u(&sh_h[0][u]),          sm2u(&sh_h[1][u]) };
    const uint32_t pA[2]  = { sm2u(&sh_P[0][rank][lane]), sm2u(&sh_P[1][rank][lane]) };
    const uint32_t eA[2]  = { sm2u(&sh_enc[0][rank]),     sm2u(&sh_enc[1][rank]) };

    float prev = 0.f, hold = 0.f, y = 0.f;

    for (int t = 0; t < Tn; ++t){
        const int bq = t & 1;
        const uint32_t pc = (uint32_t)((t >> 1) & 1);

        // arm current-phase mbarriers (arrive=1 + expected remote tx bytes)
        if (tid == 0){
            mbar_arrive_expect(mbH[bq], 224*4);   // h: 7 remote lanes x 32 units
            mbar_arrive_expect(mbP[bq], 256*4);   // pv: 8 srcs x 32 cols (incl self)
            mbar_arrive_expect(mbE[bq], CL*8);    // enc: 8 srcs x u64 (incl self)
        }

        // ---------- gates: need full h(t-1) ----------
        if (t > 0) mbar_wait(mbH[bq ^ 1], (uint32_t)(((t - 1) >> 1) & 1));
        float ahr = 0.f, ahz = 0.f, ahn = 0.f;
        {
            const float* hp = sh_h[bq ^ 1];
#pragma unroll
            for (int m = 0; m < 32; m++){
                float hv = hp[s + 8*m];           // conflict-free broadcast LDS
                ahr = fmaf(whr[m], hv, ahr);
                ahz = fmaf(whz[m], hv, ahz);
                ahn = fmaf(whn[m], hv, ahn);
            }
        }
#pragma unroll
        for (int off = 4; off >= 1; off >>= 1){
            ahr += __shfl_xor_sync(0xffffffffu, ahr, off);
            ahz += __shfl_xor_sync(0xffffffffu, ahz, off);
            ahn += __shfl_xor_sync(0xffffffffu, ahn, off);
        }
        float rg   = fsigm(ahr + cr + wpr*prev);
        float zg   = fsigm(ahz + cz + wpz*prev);
        float ng   = ftanh(cn + wpn*prev + rg*(ahn + bhn));
        float hnew = fmaf(zg, hold - ng, ng);     // (1-z)n + z*hold
        hold = hnew;

        // local slice store (s==rank keeps this CTA's copy)
        if (s == rank) sh_h[bq][u] = hnew;
        // anti-WAR fence: all threads past the h(t-1)/P(t-1)/enc(t-1) reads
        // before ANY send of step-t data leaves this CTA
        __syncthreads();
        // distribute h(t): lane s -> CTA s (7 remote one-sided stores)
        if (s != rank) st_async_f32(hA[bq], mbH[bq], (uint32_t)s, hnew);

        // partial logits from LOCAL h slice, one-sided scatter to owner CTA
        float pv = 0.f;
        {
            const float* hq = sh_h[bq] + rank*32;
#pragma unroll
            for (int j2 = 0; j2 < 32; j2++) pv = fmaf(hq[j2], ow[j2], pv);
        }
        st_async_f32(pA[bq], mbP[bq], (uint32_t)(tid >> 5), pv);

        // ---------- owner side: final logits + argmax ----------
        mbar_wait(mbP[bq], pc);
        float logit = 0.f;
        if (tid < 32){
            logit = ob;
#pragma unroll
            for (int src = 0; src < CL; src++) logit += sh_P[bq][src][tid];
            float mv = logit;
#pragma unroll
            for (int off = 16; off >= 1; off >>= 1)
                mv = fmaxf(mv, __shfl_xor_sync(0xffffffffu, mv, off));
            uint32_t mask = __ballot_sync(0xffffffffu, logit == mv);
            int mi = rank*32 + (__ffs(mask) - 1);     // lowest index on ties
            if (lane == 0){
                unsigned long long enc = ((unsigned long long)ford(mv) << 8)
                                       | (unsigned long long)(255 - mi);
#pragma unroll
                for (int d = 0; d < CL; d++)
                    st_async_u64(eA[bq], mbE[bq], (uint32_t)d, enc);
            }
            // overlap the logits STG with the enc exchange latency
            logits_out[((size_t)(b*Tn + t))*256 + rank*32 + tid] = logit;
        }

        // per-frame cond reload (write half) also overlaps the E wait
        int tn1 = t + 1;
        bool boundary = (tn1 < Tn) && ((tn1 % FSn) == 0);
        if (boundary && tid < 128) sh_cond[tid] = g_cond[(b*Fn + tn1/FSn)*128 + tid];

        mbar_wait(mbE[bq], pc);

        // ---------- combine argmax, mu-law sample, de-emphasis ----------
        unsigned long long best = sh_enc[bq][0];
#pragma unroll
        for (int sc = 1; sc < CL; sc++){
            unsigned long long v2 = sh_enc[bq][sc];
            best = (v2 > best) ? v2 : best;
        }
        int idx   = 255 - (int)(best & 0xFFull);
        float v   = ((float)idx + 0.5f)*(1.f/128.f) - 1.f;
        float av  = fabsf(v);
        float smp = copysignf((exp2f(8.f*av) - 1.f)*(1.f/255.f), v);
        prev = smp;
        if (rank == 0 && tid == 0){
            y = smp + 0.97f*y;
            wav_out[b*Tn + t] = y;
        }
        if (boundary){
            __syncthreads();      // cond writes visible before recompute
            calc_consts();
        }
    }
}

// ---------------- launch ----------------
extern "C" void kernel_launch(void* const* d_in, const int* in_sizes, int n_in,
                              void* d_out, int out_size)
{
    const float* features = (const float*)d_in[0];
    const float* c1w = (const float*)d_in[1];
    const float* c1b = (const float*)d_in[2];
    const float* c2w = (const float*)d_in[3];
    const float* c2b = (const float*)d_in[4];
    const float* f1w = (const float*)d_in[5];
    const float* f1b = (const float*)d_in[6];
    const float* f2w = (const float*)d_in[7];
    const float* f2b = (const float*)d_in[8];
    const float* wi  = (const float*)d_in[9];
    const float* wh  = (const float*)d_in[10];
    const float* bi  = (const float*)d_in[11];
    const float* bh  = (const float*)d_in[12];
    const float* oww = (const float*)d_in[13];
    const float* obb = (const float*)d_in[14];

    float* out    = (float*)d_out;
    float* wav    = out;                       // (B, T, 1) flattened first
    float* logits = out + (size_t)Bn*Tn;       // (B, T, 256) after

    frn_conv1<<<Bn*Fn, 128>>>(features, c1w, c1b);
    frn_conv2<<<Bn*Fn, 128>>>(c2w, c2b);
    frn_fc   <<<Bn*Fn, 128>>>(f1w, f1b, f2w, f2b);
    gru_kernel<<<Bn*CL, 256>>>(wi, wh, bi, bh, oww, obb, wav, logits);
}